// round 15
// baseline (speedup 1.0000x reference)
#include <cuda_runtime.h>
#include <math_constants.h>

// Hausdorff loss: x,y (8, 4096, 3) fp32 -> scalar, ONE kernel launch.
// FUSED BIDIRECTIONAL (one distance matrix serves both directions):
//   u = |x|^2 - 2 x.y  (3 FFMA, chain seeded with |x|^2)
//   row (x-side): m_k = min(m_k, u + w_j)           [FADD + FMNMX]
//   col (y-side): c_j = min_k(u); flushed per 8-target block as
//                 v = max(c_j + w_j, 0)  ->  REDG.MAX(~bits(v)) to global
//                 col slab. Fire-and-forget: NO shfl, NO smem RMW (this is
//                 what killed fusion attempts #1/#2).
// Half the pairs of the two-direction scan: 4.25 fma-ops/pair -> 33.4us floor.
//
// Complement-bits merge: for v >= 0, min(bits) == ~max(~bits), identity 0
// ==> zero-initialized __device__ slabs, no init kernel. Sentinel targets
// (0,0,0,+INF) flush key ~bits(INF) = 0x807FFFFF which loses every max.
//
// Decomposition: 8 batches x 74 target-chunks = 592 CTAs = 4/SM (148*4).
// Per-batch last-done CTA (of 74) reduces row+col slabs (8192 words),
// restores zeros; global last-done emits the scalar and resets all state.

#define NB 8
#define V  4096
#define TC 74                         // 8*74 = 592 CTAs = 148*4
#define THREADS 256
#define QPT 4
#define NPASS (V / (QPT * THREADS))   // 4
#define NTP 56                        // padded targets per chunk (7 blocks of 8)
#define NSB (NTP / 8)
#define NWARP (THREADS / 32)

__device__ unsigned g_row[NB * V];    // zero-init == identity for max(~bits)
__device__ unsigned g_col[NB * V];    // zero-init == identity for max(~bits)
__device__ unsigned g_max[NB];
__device__ unsigned g_slab_done[NB];
__device__ unsigned g_done;

__global__ void __launch_bounds__(THREADS, 4)
hd_main_kernel(const float* __restrict__ X, const float* __restrict__ Y,
               float* __restrict__ out) {
    __shared__ float4 sT[NTP];
    __shared__ float wmax[NWARP];
    __shared__ int s_role;

    const int tc = blockIdx.x;           // 0..73
    const int b  = blockIdx.y;
    const float* __restrict__ Xb = X + (size_t)b * V * 3;
    const float* __restrict__ Yb = Y + (size_t)b * V * 3;
    unsigned* __restrict__ rowslab = g_row + (size_t)b * V;
    unsigned* __restrict__ colslab = g_col + (size_t)b * V;

    const int t0 = (tc * V) / TC;
    const int nt = ((tc + 1) * V) / TC - t0;   // 55 or 56
    const int tid = threadIdx.x;
    const int wid = tid >> 5;
    const int lid = tid & 31;

    // Stage targets (y-points): (x, y, z, |t|^2); pad with (0,0,0,+INF).
    if (tid < NTP) {
        float4 v = make_float4(0.0f, 0.0f, 0.0f, CUDART_INF_F);
        if (tid < nt) {
            const int g = t0 + tid;
            const float tx = Yb[g * 3 + 0];
            const float ty = Yb[g * 3 + 1];
            const float tz = Yb[g * 3 + 2];
            v = make_float4(tx, ty, tz, tx * tx + ty * ty + tz * tz);
        }
        sT[tid] = v;
    }
    __syncthreads();

    #pragma unroll 1
    for (int p = 0; p < NPASS; p++) {
        const int qb = p * (QPT * THREADS) + tid;

        float ax[QPT], ay[QPT], az[QPT], x2[QPT], m[QPT];
        #pragma unroll
        for (int k = 0; k < QPT; k++) {
            const int q = qb + k * THREADS;
            const float qx = Xb[q * 3 + 0];
            const float qy = Xb[q * 3 + 1];
            const float qz = Xb[q * 3 + 2];
            ax[k] = -2.0f * qx; ay[k] = -2.0f * qy; az[k] = -2.0f * qz;
            x2[k] = qx * qx + qy * qy + qz * qz;
            m[k]  = CUDART_INF_F;
        }

        #pragma unroll 1
        for (int sb = 0; sb < NSB; sb++) {
            float c[8];
            #pragma unroll
            for (int j = 0; j < 8; j++) c[j] = CUDART_INF_F;

            #pragma unroll
            for (int j = 0; j < 8; j++) {
                const float4 t = sT[sb * 8 + j];   // broadcast LDS.128
                #pragma unroll
                for (int k = 0; k < QPT; k++) {
                    // u = |x|^2 - 2 x.y
                    const float u = fmaf(ax[k], t.x,
                                    fmaf(ay[k], t.y,
                                    fmaf(az[k], t.z, x2[k])));
                    m[k] = fminf(m[k], u + t.w);   // row: d^2 = u + |y|^2
                    c[j] = fminf(c[j], u);         // col partial (4 queries)
                }
            }

            // Fire-and-forget col flush: v = max(c + w, 0) is this thread's
            // min d^2 for target sb*8+j over its 4 queries. REDG.MAX merges.
            // Sentinel targets flush ~bits(INF) which never wins.
            #pragma unroll
            for (int j = 0; j < 8; j++) {
                const int tj = sb * 8 + j;
                const float v = fmaxf(c[j] + sT[tj].w, 0.0f);
                atomicMax(&colslab[t0 + tj], ~__float_as_uint(v));
            }
        }

        #pragma unroll
        for (int k = 0; k < QPT; k++) {
            const float s = fmaxf(m[k], 0.0f);
            atomicMax(&rowslab[qb + k * THREADS], ~__float_as_uint(s));
        }
    }

    // NOTE: padded flushes target indices [t0+nt, t0+56) which belong to the
    // next chunk — harmless, their keys (~bits(INF)) lose every max.

    // ---- per-batch last-done CTA (of 74) reduces row+col slabs ----
    __threadfence();
    __syncthreads();
    if (tid == 0)
        s_role = (atomicAdd(&g_slab_done[b], 1u) == TC - 1);
    __syncthreads();
    if (!s_role) return;

    __threadfence();   // acquire: all 74 CTAs' atomics visible

    float mm = 0.0f;
    {
        uint4* __restrict__ r4 = reinterpret_cast<uint4*>(rowslab);
        uint4* __restrict__ c4 = reinterpret_cast<uint4*>(colslab);
        #pragma unroll
        for (int i = tid; i < V / 4; i += THREADS) {
            const uint4 wr = r4[i];
            mm = fmaxf(mm, __uint_as_float(~wr.x));
            mm = fmaxf(mm, __uint_as_float(~wr.y));
            mm = fmaxf(mm, __uint_as_float(~wr.z));
            mm = fmaxf(mm, __uint_as_float(~wr.w));
            r4[i] = make_uint4(0u, 0u, 0u, 0u);      // restore identity
            const uint4 wc = c4[i];
            mm = fmaxf(mm, __uint_as_float(~wc.x));
            mm = fmaxf(mm, __uint_as_float(~wc.y));
            mm = fmaxf(mm, __uint_as_float(~wc.z));
            mm = fmaxf(mm, __uint_as_float(~wc.w));
            c4[i] = make_uint4(0u, 0u, 0u, 0u);      // restore identity
        }
    }
    #pragma unroll
    for (int off = 16; off > 0; off >>= 1)
        mm = fmaxf(mm, __shfl_xor_sync(0xffffffffu, mm, off));
    if (lid == 0) wmax[wid] = mm;
    __syncthreads();

    if (tid == 0) {
        float mx = wmax[0];
        #pragma unroll
        for (int w = 1; w < NWARP; w++) mx = fmaxf(mx, wmax[w]);
        atomicMax(&g_max[b], __float_as_uint(mx));   // nonneg bits
        g_slab_done[b] = 0u;                         // restore (all 74 arrived)

        __threadfence();
        if (atomicAdd(&g_done, 1u) == NB - 1) {      // global last: finalize
            __threadfence();
            float s = 0.0f;
            #pragma unroll
            for (int i = 0; i < NB; i++) {
                s += sqrtf(__uint_as_float(g_max[i]));
                g_max[i] = 0u;                       // restore
            }
            out[0] = s * (1.0f / (float)NB);         // LOSS_WEIGHT = 1.0
            g_done = 0u;                             // restore
        }
    }
}

extern "C" void kernel_launch(void* const* d_in, const int* in_sizes, int n_in,
                              void* d_out, int out_size) {
    const float* x = (const float*)d_in[0];
    const float* y = (const float*)d_in[1];
    float* out = (float*)d_out;

    dim3 grid(TC, NB);
    hd_main_kernel<<<grid, THREADS>>>(x, y, out);
}

// round 17
// speedup vs baseline: 1.5573x; 1.5573x over previous
#include <cuda_runtime.h>
#include <math_constants.h>

// Hausdorff loss: x,y (8, 4096, 3) fp32 -> scalar, ONE kernel launch.
// FUSED BIDIRECTIONAL (one distance matrix serves both directions):
//   u = |x|^2 - 2 x.y      (3-FFMA chain seeded with |x|^2)
//   row (x-side): m_k = min(m_k, u + w_j)     [FADD + FMNMX]
//   col (y-side): c_j = min_k(u); flushed per 8-target sub-block as
//                 v = max(c_j + w_j, 0)  (NONNEGATIVE -> u32 bit ordering
//                 == float ordering) -> ONE __reduce_min_sync(u32) per
//                 target, lane0 -> per-warp private smem cell.
// R16 bug fixed: s32 ordering of float bits is REVERSED for negatives;
// reducing the clamped nonneg d^2 with u32 min is exact.
//
// 4.5 fma-pipe ops/pair, half the pairs of a two-direction scan.
// No in-loop shfl chains (killed fusion #2), no global atomic contention
// (killed #3), no per-iteration REDUX dependency (killed #1).
//
// Row: complement-bits atomicMax slab (identity 0 -> zero-init, no init
// kernel); per-batch last-done CTA (of 74) reduces + restores; global
// last-done emits the scalar and resets all state (graph-replay safe).
//
// Decomposition: 8 batches x 74 target-chunks = 592 CTAs = 4/SM (148*4).

#define NB 8
#define V  4096
#define TC 74                         // 8*74 = 592 CTAs = 148*4
#define THREADS 256
#define QPT 4
#define NPASS (V / (QPT * THREADS))   // 4
#define NTP 56                        // padded targets per chunk (7 blocks of 8)
#define NSB (NTP / 8)
#define NWARP (THREADS / 32)

__device__ unsigned g_row[NB * V];    // zero-init == identity for max(~bits)
__device__ unsigned g_max[NB];
__device__ unsigned g_slab_done[NB];
__device__ unsigned g_done;

__global__ void __launch_bounds__(THREADS, 4)
hd_main_kernel(const float* __restrict__ X, const float* __restrict__ Y,
               float* __restrict__ out) {
    __shared__ float4 sT[NTP];
    __shared__ unsigned scol[NTP][NWARP];  // per-warp col-min d^2 bits (nonneg)
    __shared__ float wmax[NWARP];
    __shared__ int s_role;

    const int tc = blockIdx.x;           // 0..73
    const int b  = blockIdx.y;
    const float* __restrict__ Xb = X + (size_t)b * V * 3;
    const float* __restrict__ Yb = Y + (size_t)b * V * 3;
    unsigned* __restrict__ rowslab = g_row + (size_t)b * V;

    const int t0 = (tc * V) / TC;
    const int nt = ((tc + 1) * V) / TC - t0;   // 55 or 56
    const int tid = threadIdx.x;
    const int wid = tid >> 5;
    const int lid = tid & 31;

    // Stage targets (y-points): (x, y, z, |t|^2); pad with (0,0,0,+INF).
    // Sentinel rows see u + INF (never the min); sentinel col flushes are
    // bits(INF), which never win the u32 min. Fold is guarded by tid < nt.
    if (tid < NTP) {
        float4 v = make_float4(0.0f, 0.0f, 0.0f, CUDART_INF_F);
        if (tid < nt) {
            const int g = t0 + tid;
            const float tx = Yb[g * 3 + 0];
            const float ty = Yb[g * 3 + 1];
            const float tz = Yb[g * 3 + 2];
            v = make_float4(tx, ty, tz, tx * tx + ty * ty + tz * tz);
        }
        sT[tid] = v;
    }
    for (int i = tid; i < NTP * NWARP; i += THREADS)
        (&scol[0][0])[i] = 0x7F800000u;   // bits(+INF)
    __syncthreads();

    #pragma unroll 1
    for (int p = 0; p < NPASS; p++) {
        const int qb = p * (QPT * THREADS) + tid;

        float ax[QPT], ay[QPT], az[QPT], x2[QPT], m[QPT];
        #pragma unroll
        for (int k = 0; k < QPT; k++) {
            const int q = qb + k * THREADS;
            const float qx = Xb[q * 3 + 0];
            const float qy = Xb[q * 3 + 1];
            const float qz = Xb[q * 3 + 2];
            ax[k] = -2.0f * qx; ay[k] = -2.0f * qy; az[k] = -2.0f * qz;
            x2[k] = qx * qx + qy * qy + qz * qz;
            m[k]  = CUDART_INF_F;
        }

        #pragma unroll 1
        for (int sb = 0; sb < NSB; sb++) {
            float c[8];
            #pragma unroll
            for (int j = 0; j < 8; j++) c[j] = CUDART_INF_F;

            #pragma unroll
            for (int j = 0; j < 8; j++) {
                const float4 t = sT[sb * 8 + j];   // broadcast LDS.128
                #pragma unroll
                for (int k = 0; k < QPT; k++) {
                    // u = |x|^2 - 2 x.y
                    const float u = fmaf(ax[k], t.x,
                                    fmaf(ay[k], t.y,
                                    fmaf(az[k], t.z, x2[k])));
                    m[k] = fminf(m[k], u + t.w);   // row: d^2 = u + |y|^2
                    c[j] = fminf(c[j], u);         // col partial
                }
            }

            // Flush: clamp to nonneg d^2, then ONE u32 REDUX per target;
            // lane0 merges into this warp's private cell.
            #pragma unroll
            for (int j = 0; j < 8; j++) {
                const int tj = sb * 8 + j;
                const float v = fmaxf(c[j] + sT[tj].w, 0.0f);   // nonneg
                const unsigned r = __reduce_min_sync(0xffffffffu,
                                                     __float_as_uint(v));
                if (lid == 0)
                    scol[tj][wid] = min(scol[tj][wid], r);
            }
        }

        #pragma unroll
        for (int k = 0; k < QPT; k++) {
            const float s = fmaxf(m[k], 0.0f);
            // min over chunks == ~(max over chunks of ~bits); identity 0.
            atomicMax(&rowslab[qb + k * THREADS], ~__float_as_uint(s));
        }
    }

    // ---- y-side fold: column results are COMPLETE in this CTA ----
    __syncthreads();
    float my = 0.0f;
    if (tid < nt) {
        unsigned u = scol[tid][0];
        #pragma unroll
        for (int w = 1; w < NWARP; w++) u = min(u, scol[tid][w]);
        my = __uint_as_float(u);               // NN^2 for target t0+tid
    }
    #pragma unroll
    for (int off = 16; off > 0; off >>= 1)
        my = fmaxf(my, __shfl_xor_sync(0xffffffffu, my, off));
    if (lid == 0) wmax[wid] = my;
    __syncthreads();
    if (tid == 0) {
        float mx = wmax[0];
        #pragma unroll
        for (int w = 1; w < NWARP; w++) mx = fmaxf(mx, wmax[w]);
        atomicMax(&g_max[b], __float_as_uint(mx));  // nonneg bits
    }

    // ---- per-batch last-done CTA (of 74) reduces the row slab ----
    __threadfence();
    __syncthreads();
    if (tid == 0)
        s_role = (atomicAdd(&g_slab_done[b], 1u) == TC - 1);
    __syncthreads();
    if (!s_role) return;

    __threadfence();   // acquire: all 74 CTAs' atomics visible

    float mm = 0.0f;
    {
        uint4* __restrict__ r4 = reinterpret_cast<uint4*>(rowslab);
        #pragma unroll
        for (int i = tid; i < V / 4; i += THREADS) {
            const uint4 w = r4[i];
            mm = fmaxf(mm, __uint_as_float(~w.x));
            mm = fmaxf(mm, __uint_as_float(~w.y));
            mm = fmaxf(mm, __uint_as_float(~w.z));
            mm = fmaxf(mm, __uint_as_float(~w.w));
            r4[i] = make_uint4(0u, 0u, 0u, 0u);   // restore identity
        }
    }
    #pragma unroll
    for (int off = 16; off > 0; off >>= 1)
        mm = fmaxf(mm, __shfl_xor_sync(0xffffffffu, mm, off));
    if (lid == 0) wmax[wid] = mm;
    __syncthreads();

    if (tid == 0) {
        float mx = wmax[0];
        #pragma unroll
        for (int w = 1; w < NWARP; w++) mx = fmaxf(mx, wmax[w]);
        atomicMax(&g_max[b], __float_as_uint(mx));
        g_slab_done[b] = 0u;                   // restore (all 74 arrived)

        __threadfence();
        if (atomicAdd(&g_done, 1u) == NB - 1) {   // global last: finalize
            __threadfence();
            float s = 0.0f;
            #pragma unroll
            for (int i = 0; i < NB; i++) {
                s += sqrtf(__uint_as_float(g_max[i]));
                g_max[i] = 0u;                 // restore
            }
            out[0] = s * (1.0f / (float)NB);   // LOSS_WEIGHT = 1.0
            g_done = 0u;                       // restore
        }
    }
}

extern "C" void kernel_launch(void* const* d_in, const int* in_sizes, int n_in,
                              void* d_out, int out_size) {
    const float* x = (const float*)d_in[0];
    const float* y = (const float*)d_in[1];
    float* out = (float*)d_out;

    dim3 grid(TC, NB);
    hd_main_kernel<<<grid, THREADS>>>(x, y, out);
}